// round 15
// baseline (speedup 1.0000x reference)
#include <cuda_runtime.h>
#include <math.h>
#include <stdint.h>

#define IMG 32
#define HDIM 1024
#define WDIM 1024
#define LOSS_THR 120.0f
#define MM_BLOCKS 1024
#define NWBG 32          // 1024 / 32 px per CTA
#define NHB 128

// ---- global scratch (module-scope: no runtime allocations) ----
__device__ float g_part_max[MM_BLOCKS];
__device__ float g_part_min[MM_BLOCKS];
__device__ unsigned int g_count = 0;   // self-resetting -> deterministic across graph replays
__device__ float g_mx;
__device__ float g_mn;

__device__ __forceinline__ unsigned int smem_u32(const void* p) {
    return (unsigned int)__cvta_generic_to_shared(p);
}

// Phase A: global min/max of width-deltas xd = x - shift_right(x).
__global__ __launch_bounds__(256) void minmax_kernel(const float* __restrict__ x) {
    const int tid = threadIdx.x;
    const int lane = tid & 31;
    const int warp = tid >> 5;
    const int base = (blockIdx.x * blockDim.x + tid) << 5;   // 32 floats per thread

    float4 v[8];
    #pragma unroll
    for (int j = 0; j < 8; j++)
        v[j] = *reinterpret_cast<const float4*>(x + base + (j << 2));
    float left = ((base & (WDIM - 1)) == 0) ? 0.0f : __ldg(x + base - 1);

    float vmax = -3.402823466e38f, vmin = 3.402823466e38f;
    #pragma unroll
    for (int j = 0; j < 8; j++) {
        float d0 = v[j].x - left;
        float d1 = v[j].y - v[j].x;
        float d2 = v[j].z - v[j].y;
        float d3 = v[j].w - v[j].z;
        left = v[j].w;
        vmax = fmaxf(fmaxf(fmaxf(d0, d1), fmaxf(d2, d3)), vmax);
        vmin = fminf(fminf(fminf(d0, d1), fminf(d2, d3)), vmin);
    }
    for (int o = 16; o; o >>= 1) {
        vmax = fmaxf(vmax, __shfl_xor_sync(0xFFFFFFFFu, vmax, o));
        vmin = fminf(vmin, __shfl_xor_sync(0xFFFFFFFFu, vmin, o));
    }
    __shared__ float swmax[8], swmin[8];
    if (lane == 0) { swmax[warp] = vmax; swmin[warp] = vmin; }
    __syncthreads();
    if (tid == 0) {
        float bmax = swmax[0], bmin = swmin[0];
        #pragma unroll
        for (int k = 1; k < 8; k++) {
            bmax = fmaxf(bmax, swmax[k]);
            bmin = fminf(bmin, swmin[k]);
        }
        g_part_max[blockIdx.x] = bmax;
        g_part_min[blockIdx.x] = bmin;
    }

    __shared__ bool isLast;
    if (tid == 0) {
        __threadfence();
        unsigned int c = atomicAdd(&g_count, 1u);
        isLast = (c == gridDim.x - 1);
    }
    __syncthreads();
    if (isLast) {
        float mx = -3.402823466e38f, mn = 3.402823466e38f;
        for (int j = tid; j < MM_BLOCKS; j += blockDim.x) {
            mx = fmaxf(mx, g_part_max[j]);
            mn = fminf(mn, g_part_min[j]);
        }
        for (int o = 16; o; o >>= 1) {
            mx = fmaxf(mx, __shfl_xor_sync(0xFFFFFFFFu, mx, o));
            mn = fminf(mn, __shfl_xor_sync(0xFFFFFFFFu, mn, o));
        }
        if (lane == 0) { swmax[warp] = mx; swmin[warp] = mn; }
        __syncthreads();
        if (tid == 0) {
            float bmax = swmax[0], bmin = swmin[0];
            #pragma unroll
            for (int k = 1; k < 8; k++) {
                bmax = fmaxf(bmax, swmax[k]);
                bmin = fminf(bmin, swmin[k]);
            }
            g_mx = bmax;
            g_mn = bmin;
            g_count = 0;  // reset for next replay
        }
    }
}

// Phase B: one CTA per (hb, group of 4 adjacent 8x8 blocks).
// cp.async staging; q-first projection; register carry; strength-reduced I/O loops.
__global__ __launch_bounds__(256, 4) void block_kernel(const float* __restrict__ x,
                                                       float* __restrict__ out) {
    __shared__ float ss[256][36];       // raw x strips (img*8+row) x 32 px; later final output
    __shared__ float scarry[256];       // left-boundary pixel per strip
    __shared__ float sa[2][8][36];      // d1 of imgs 0,1: [img][row][wb*8+c]
    __shared__ float sS[4][5];          // Gram scalars per sub-block
    __shared__ int   sdegen[4];

    const int tid = threadIdx.x;
    const int lane = tid & 31;
    const int warp = tid >> 5;
    const int img = tid >> 3;          // image 0..31
    const int row = tid & 7;           // row 0..7
    const int wbg = blockIdx.x & (NWBG - 1);
    const int hb = blockIdx.x >> 5;

    const float mx = g_mx, mn = g_mn;
    const bool neq = (mx != mn);
    const float scale = neq ? __fdiv_rn(65535.0f, __fsub_rn(mx, mn)) : 1.0f;
    const float s_inv = __fdiv_rn(1.0f, scale);
    const float m = neq ? mn : 0.0f;
    const float lsb = exp2f(rintf(log2f(__fdiv_rn(mx, 32768.0f))) + 1.0f);
    const float rlsb = __fdiv_rn(1.0f, lsb);

    // I/O loop geometry (loop-invariant parts; per-k: +4<<20 global, +32 rows smem)
    const int io_sr = (tid >> 3) & 7;           // spatial row (invariant over k)
    const int io_j4 = (tid & 7) << 2;           // float offset within strip (invariant)
    const long io_goff = ((long)(tid >> 6) << 20)
                       + (((hb << 3) + io_sr) << 10) + (wbg << 5) + io_j4;
    const int io_srow = tid >> 3;               // starting smem strip

    // ---- coalesced staging: global -> smem via cp.async (RF-bypass) ----
    {
        const float* gp = x + io_goff;
        unsigned int sp_ = smem_u32(&ss[io_srow][io_j4]);
        #pragma unroll
        for (int k = 0; k < 8; k++) {
            asm volatile("cp.async.cg.shared.global [%0], [%1], 16;\n"
                         :: "r"(sp_), "l"(gp) : "memory");
            gp += (4l << 20);
            sp_ += 32 * 36 * 4;
        }
    }
    asm volatile("cp.async.commit_group;\n" ::: "memory");
    scarry[tid] = (wbg > 0)
        ? __ldg(x + (img << 20) + (((hb << 3) + row) << 10) + (wbg << 5) - 1)
        : 0.0f;
    asm volatile("cp.async.wait_group 0;\n" ::: "memory");
    __syncthreads();

    // ---- stage A0 (128 threads): d1 of images 0,1 -> sa (4 px per thread) ----
    if (tid < 128) {
        const int im = tid >> 6;              // image 0/1
        const int ar = (tid >> 3) & 7;        // row
        const int aw = tid & 7;               // 4-px chunk 0..7
        const int strip = (im << 3) + ar;
        float4 v = *reinterpret_cast<const float4*>(&ss[strip][aw << 2]);
        float xv[4] = {v.x, v.y, v.z, v.w};
        float prev = (aw == 0) ? scarry[strip] : ss[strip][(aw << 2) - 1];
        float dq[4];
        #pragma unroll
        for (int c = 0; c < 4; c++) {
            float xd = __fsub_rn(xv[c], prev);
            prev = xv[c];
            if (neq) {
                float q = rintf(__fmul_rn(__fsub_rn(xd, mn), scale));
                dq[c] = __fadd_rn(__fmul_rn(q, s_inv), m);
            } else {
                dq[c] = xd;
            }
        }
        *reinterpret_cast<float4*>(&sa[im][ar][aw << 2]) =
            make_float4(dq[0], dq[1], dq[2], dq[3]);
    }
    __syncthreads();

    // ---- stage A1: Gram + degeneracy, warp w -> sub-block w ----
    if (warp < 4) {
        const int wb = warp;
        int r0 = lane >> 3, c0 = (wb << 3) + (lane & 7);
        float a1a = sa[0][r0][c0],     a1b = sa[0][r0 + 4][c0];
        float a2a = sa[1][r0][c0],     a2b = sa[1][r0 + 4][c0];
        float S11 = a1a * a1a + a1b * a1b;
        float S12 = a1a * a2a + a1b * a2b;
        float S1  = a1a + a1b;
        float S22 = a2a * a2a + a2b * a2b;
        float S2  = a2a + a2b;
        float mx1 = fmaxf(a1a, a1b), mn1 = fminf(a1a, a1b);
        float mx2 = fmaxf(a2a, a2b), mn2 = fminf(a2a, a2b);
        for (int o = 16; o; o >>= 1) {
            S11 += __shfl_xor_sync(0xFFFFFFFFu, S11, o);
            S12 += __shfl_xor_sync(0xFFFFFFFFu, S12, o);
            S1  += __shfl_xor_sync(0xFFFFFFFFu, S1, o);
            S22 += __shfl_xor_sync(0xFFFFFFFFu, S22, o);
            S2  += __shfl_xor_sync(0xFFFFFFFFu, S2, o);
            mx1 = fmaxf(mx1, __shfl_xor_sync(0xFFFFFFFFu, mx1, o));
            mn1 = fminf(mn1, __shfl_xor_sync(0xFFFFFFFFu, mn1, o));
            mx2 = fmaxf(mx2, __shfl_xor_sync(0xFFFFFFFFu, mx2, o));
            mn2 = fminf(mn2, __shfl_xor_sync(0xFFFFFFFFu, mn2, o));
        }
        if (lane == 0) {
            sS[wb][0] = S11; sS[wb][1] = S12; sS[wb][2] = S1;
            sS[wb][3] = S22; sS[wb][4] = S2;
            sdegen[wb] = (((mx1 - mn1) < 1e-6f) && ((mx2 - mn2) < 1e-6f)) ? 1 : 0;
        }
    }
    __syncthreads();

    // ---- fused stage: register carry of raw x; unroll 2 for ILP ----
    {
        float carry = scarry[tid];
        #pragma unroll 2
        for (int wb = 0; wb < 4; wb++) {
            // cofactors of AT_A (uniform per warp; identity when det==0)
            const float A00 = sS[wb][0], A01 = sS[wb][1], A02 = sS[wb][2];
            const float A11 = sS[wb][3], A12 = sS[wb][4], A22 = 64.0f;
            float C00 = A11 * A22 - A12 * A12;
            float C01 = A02 * A12 - A01 * A22;
            float C02 = A01 * A12 - A02 * A11;
            float C11 = A00 * A22 - A02 * A02;
            float C12 = A01 * A02 - A00 * A12;
            float C22 = A00 * A11 - A01 * A01;
            float det = A00 * C00 + A01 * C01 + A02 * C02;
            float rdet;
            if (det == 0.0f) {
                C00 = 1.0f; C01 = 0.0f; C02 = 0.0f;
                C11 = 1.0f; C12 = 0.0f; C22 = 1.0f;
                rdet = 1.0f;
            } else {
                rdet = __fdiv_rn(1.0f, det);
            }

            float4 v0 = *reinterpret_cast<const float4*>(&ss[tid][wb << 3]);
            float4 v1 = *reinterpret_cast<const float4*>(&ss[tid][(wb << 3) + 4]);
            float xv[8] = {v0.x, v0.y, v0.z, v0.w, v1.x, v1.y, v1.z, v1.w};
            const float lcar = carry;       // raw left pixel for this block
            carry = xv[7];                  // propagate RAW x (not output!)

            // dequant own 8 px (registers)
            float d1v[8];
            {
                float prev = lcar;
                #pragma unroll
                for (int c = 0; c < 8; c++) {
                    float xd = __fsub_rn(xv[c], prev);
                    prev = xv[c];
                    if (neq) {
                        float q = rintf(__fmul_rn(__fsub_rn(xd, mn), scale));
                        d1v[c] = __fadd_rn(__fmul_rn(q, s_inv), m);
                    } else {
                        d1v[c] = xd;
                    }
                }
            }

            // a1/a2 for this row
            float4 a1a4 = *reinterpret_cast<const float4*>(&sa[0][row][wb << 3]);
            float4 a1b4 = *reinterpret_cast<const float4*>(&sa[0][row][(wb << 3) + 4]);
            float4 a2a4 = *reinterpret_cast<const float4*>(&sa[1][row][wb << 3]);
            float4 a2b4 = *reinterpret_cast<const float4*>(&sa[1][row][(wb << 3) + 4]);
            float av1[8] = {a1a4.x, a1a4.y, a1a4.z, a1a4.w, a1b4.x, a1b4.y, a1b4.z, a1b4.w};
            float av2[8] = {a2a4.x, a2a4.y, a2a4.z, a2a4.w, a2b4.x, a2b4.y, a2b4.z, a2b4.w};

            // q = A^T d : three cheap dots (3 FMA/px)
            float t0 = 0.0f, t1 = 0.0f, t2 = 0.0f;
            #pragma unroll
            for (int c = 0; c < 8; c++) {
                t0 += av1[c] * d1v[c];
                t1 += av2[c] * d1v[c];
                t2 += d1v[c];
            }
            // reduce over the 8 lanes of this image: every lane ends with same q
            #pragma unroll
            for (int o = 4; o; o >>= 1) {
                t0 += __shfl_xor_sync(0xFFFFFFFFu, t0, o);
                t1 += __shfl_xor_sync(0xFFFFFFFFu, t1, o);
                t2 += __shfl_xor_sync(0xFFFFFFFFu, t2, o);
            }
            // p = inv * q (applied once, not per-pixel)
            const float p0 = (C00 * t0 + C01 * t1 + C02 * t2) * rdet;
            const float p1 = (C01 * t0 + C11 * t1 + C12 * t2) * rdet;
            const float p2 = (C02 * t0 + C12 * t1 + C22 * t2) * rdet;

            // reconstruct + quantize + loss
            float r1v[8];
            float loss = 0.0f;
            #pragma unroll
            for (int c = 0; c < 8; c++) {
                float r = av1[c] * p0 + av2[c] * p1 + p2;
                r1v[c] = __fmul_rn(rintf(__fmul_rn(r, rlsb)), lsb);
                float d = d1v[c] - r1v[c];
                loss += d * d;
            }
            #pragma unroll
            for (int o = 4; o; o >>= 1)
                loss += __shfl_xor_sync(0xFFFFFFFFu, loss, o);

            bool sel = (sdegen[wb] == 0) && (loss <= LOSS_THR);
            float ov[8];
            #pragma unroll
            for (int c = 0; c < 8; c++) {
                float rr = sel ? r1v[c] : d1v[c];
                float xl = (c == 0) ? lcar : xv[c - 1];
                ov[c] = __fadd_rn(rr, xl);
            }
            *reinterpret_cast<float4*>(&ss[tid][wb << 3]) =
                make_float4(ov[0], ov[1], ov[2], ov[3]);
            *reinterpret_cast<float4*>(&ss[tid][(wb << 3) + 4]) =
                make_float4(ov[4], ov[5], ov[6], ov[7]);
        }
    }
    __syncthreads();

    // ---- coalesced staged store: smem -> global (strength-reduced) ----
    {
        float* op = out + io_goff;
        const float* sp = &ss[io_srow][io_j4];
        #pragma unroll
        for (int k = 0; k < 8; k++) {
            float4 v = *reinterpret_cast<const float4*>(sp);
            *reinterpret_cast<float4*>(op) = v;
            op += (4l << 20);
            sp += 32 * 36;
        }
    }
}

extern "C" void kernel_launch(void* const* d_in, const int* in_sizes, int n_in,
                              void* d_out, int out_size) {
    const float* x = (const float*)d_in[0];
    float* out = (float*)d_out;
    (void)in_sizes; (void)n_in; (void)out_size;

    minmax_kernel<<<MM_BLOCKS, 256>>>(x);
    block_kernel<<<NHB * NWBG, 256>>>(x, out);
}

// round 16
// speedup vs baseline: 1.0090x; 1.0090x over previous
#include <cuda_runtime.h>
#include <math.h>
#include <stdint.h>

#define IMG 32
#define HDIM 1024
#define WDIM 1024
#define LOSS_THR 120.0f
#define MM_BLOCKS 1024
#define NWBG 32          // 1024 / 32 px per CTA
#define NHB 128

// ---- global scratch (module-scope: no runtime allocations) ----
__device__ float g_part_max[MM_BLOCKS];
__device__ float g_part_min[MM_BLOCKS];
__device__ unsigned int g_count = 0;   // self-resetting -> deterministic across graph replays
__device__ float g_mx;
__device__ float g_mn;

__device__ __forceinline__ unsigned int smem_u32(const void* p) {
    return (unsigned int)__cvta_generic_to_shared(p);
}

// Phase A: global min/max of width-deltas xd = x - shift_right(x).
__global__ __launch_bounds__(256) void minmax_kernel(const float* __restrict__ x) {
    const int tid = threadIdx.x;
    const int lane = tid & 31;
    const int warp = tid >> 5;
    const int base = (blockIdx.x * blockDim.x + tid) << 5;   // 32 floats per thread

    float4 v[8];
    #pragma unroll
    for (int j = 0; j < 8; j++)
        v[j] = *reinterpret_cast<const float4*>(x + base + (j << 2));
    float left = ((base & (WDIM - 1)) == 0) ? 0.0f : __ldg(x + base - 1);

    float vmax = -3.402823466e38f, vmin = 3.402823466e38f;
    #pragma unroll
    for (int j = 0; j < 8; j++) {
        float d0 = v[j].x - left;
        float d1 = v[j].y - v[j].x;
        float d2 = v[j].z - v[j].y;
        float d3 = v[j].w - v[j].z;
        left = v[j].w;
        vmax = fmaxf(fmaxf(fmaxf(d0, d1), fmaxf(d2, d3)), vmax);
        vmin = fminf(fminf(fminf(d0, d1), fminf(d2, d3)), vmin);
    }
    for (int o = 16; o; o >>= 1) {
        vmax = fmaxf(vmax, __shfl_xor_sync(0xFFFFFFFFu, vmax, o));
        vmin = fminf(vmin, __shfl_xor_sync(0xFFFFFFFFu, vmin, o));
    }
    __shared__ float swmax[8], swmin[8];
    if (lane == 0) { swmax[warp] = vmax; swmin[warp] = vmin; }
    __syncthreads();
    if (tid == 0) {
        float bmax = swmax[0], bmin = swmin[0];
        #pragma unroll
        for (int k = 1; k < 8; k++) {
            bmax = fmaxf(bmax, swmax[k]);
            bmin = fminf(bmin, swmin[k]);
        }
        g_part_max[blockIdx.x] = bmax;
        g_part_min[blockIdx.x] = bmin;
    }

    __shared__ bool isLast;
    if (tid == 0) {
        __threadfence();
        unsigned int c = atomicAdd(&g_count, 1u);
        isLast = (c == gridDim.x - 1);
    }
    __syncthreads();
    if (isLast) {
        float mx = -3.402823466e38f, mn = 3.402823466e38f;
        for (int j = tid; j < MM_BLOCKS; j += blockDim.x) {
            mx = fmaxf(mx, g_part_max[j]);
            mn = fminf(mn, g_part_min[j]);
        }
        for (int o = 16; o; o >>= 1) {
            mx = fmaxf(mx, __shfl_xor_sync(0xFFFFFFFFu, mx, o));
            mn = fminf(mn, __shfl_xor_sync(0xFFFFFFFFu, mn, o));
        }
        if (lane == 0) { swmax[warp] = mx; swmin[warp] = mn; }
        __syncthreads();
        if (tid == 0) {
            float bmax = swmax[0], bmin = swmin[0];
            #pragma unroll
            for (int k = 1; k < 8; k++) {
                bmax = fmaxf(bmax, swmax[k]);
                bmin = fminf(bmin, swmin[k]);
            }
            g_mx = bmax;
            g_mn = bmin;
            g_count = 0;  // reset for next replay
        }
    }
}

// Phase B: one CTA per (hb, group of 4 adjacent 8x8 blocks).
// Two-group cp.async staging: A0/A1 overlap the bulk load tail.
__global__ __launch_bounds__(256, 4) void block_kernel(const float* __restrict__ x,
                                                       float* __restrict__ out) {
    __shared__ float ss[256][36];       // raw x strips (img*8+row) x 32 px; later final output
    __shared__ float scarry[256];       // left-boundary pixel per strip
    __shared__ float sa[2][8][36];      // d1 of imgs 0,1: [img][row][wb*8+c]
    __shared__ float sS[4][5];          // Gram scalars per sub-block
    __shared__ int   sdegen[4];

    const int tid = threadIdx.x;
    const int lane = tid & 31;
    const int warp = tid >> 5;
    const int img = tid >> 3;          // image 0..31
    const int row = tid & 7;           // row 0..7
    const int wbg = blockIdx.x & (NWBG - 1);
    const int hb = blockIdx.x >> 5;

    const float mx = g_mx, mn = g_mn;
    const bool neq = (mx != mn);
    const float scale = neq ? __fdiv_rn(65535.0f, __fsub_rn(mx, mn)) : 1.0f;
    const float s_inv = __fdiv_rn(1.0f, scale);
    const float m = neq ? mn : 0.0f;
    const float lsb = exp2f(rintf(log2f(__fdiv_rn(mx, 32768.0f))) + 1.0f);
    const float rlsb = __fdiv_rn(1.0f, lsb);

    // I/O loop geometry (loop-invariant parts; per-k: +4<<20 global, +32 rows smem)
    const int io_sr = (tid >> 3) & 7;           // spatial row (invariant over k)
    const int io_j4 = (tid & 7) << 2;           // float offset within strip (invariant)
    const long io_goff = ((long)(tid >> 6) << 20)
                       + (((hb << 3) + io_sr) << 10) + (wbg << 5) + io_j4;
    const int io_srow = tid >> 3;               // starting smem strip

    // ---- staged load, two groups: k=0 (strips 0-31, imgs 0-3) first ----
    {
        const float* gp = x + io_goff;
        unsigned int sp_ = smem_u32(&ss[io_srow][io_j4]);
        asm volatile("cp.async.cg.shared.global [%0], [%1], 16;\n"
                     :: "r"(sp_), "l"(gp) : "memory");
        asm volatile("cp.async.commit_group;\n" ::: "memory");   // group A
        gp += (4l << 20);
        sp_ += 32 * 36 * 4;
        #pragma unroll
        for (int k = 1; k < 8; k++) {
            asm volatile("cp.async.cg.shared.global [%0], [%1], 16;\n"
                         :: "r"(sp_), "l"(gp) : "memory");
            gp += (4l << 20);
            sp_ += 32 * 36 * 4;
        }
        asm volatile("cp.async.commit_group;\n" ::: "memory");   // group B
    }
    scarry[tid] = (wbg > 0)
        ? __ldg(x + (img << 20) + (((hb << 3) + row) << 10) + (wbg << 5) - 1)
        : 0.0f;
    asm volatile("cp.async.wait_group 1;\n" ::: "memory");       // group A done
    __syncthreads();

    // ---- stage A0 (128 threads): d1 of images 0,1 -> sa (4 px per thread) ----
    // Uses only strips 0-15 (covered by group A); overlaps group B in flight.
    if (tid < 128) {
        const int im = tid >> 6;              // image 0/1
        const int ar = (tid >> 3) & 7;        // row
        const int aw = tid & 7;               // 4-px chunk 0..7
        const int strip = (im << 3) + ar;
        float4 v = *reinterpret_cast<const float4*>(&ss[strip][aw << 2]);
        float xv[4] = {v.x, v.y, v.z, v.w};
        float prev = (aw == 0) ? scarry[strip] : ss[strip][(aw << 2) - 1];
        float dq[4];
        #pragma unroll
        for (int c = 0; c < 4; c++) {
            float xd = __fsub_rn(xv[c], prev);
            prev = xv[c];
            if (neq) {
                float q = rintf(__fmul_rn(__fsub_rn(xd, mn), scale));
                dq[c] = __fadd_rn(__fmul_rn(q, s_inv), m);
            } else {
                dq[c] = xd;
            }
        }
        *reinterpret_cast<float4*>(&sa[im][ar][aw << 2]) =
            make_float4(dq[0], dq[1], dq[2], dq[3]);
    }
    __syncthreads();

    // ---- stage A1: Gram + degeneracy, warp w -> sub-block w (group B still loading) ----
    if (warp < 4) {
        const int wb = warp;
        int r0 = lane >> 3, c0 = (wb << 3) + (lane & 7);
        float a1a = sa[0][r0][c0],     a1b = sa[0][r0 + 4][c0];
        float a2a = sa[1][r0][c0],     a2b = sa[1][r0 + 4][c0];
        float S11 = a1a * a1a + a1b * a1b;
        float S12 = a1a * a2a + a1b * a2b;
        float S1  = a1a + a1b;
        float S22 = a2a * a2a + a2b * a2b;
        float S2  = a2a + a2b;
        float mx1 = fmaxf(a1a, a1b), mn1 = fminf(a1a, a1b);
        float mx2 = fmaxf(a2a, a2b), mn2 = fminf(a2a, a2b);
        for (int o = 16; o; o >>= 1) {
            S11 += __shfl_xor_sync(0xFFFFFFFFu, S11, o);
            S12 += __shfl_xor_sync(0xFFFFFFFFu, S12, o);
            S1  += __shfl_xor_sync(0xFFFFFFFFu, S1, o);
            S22 += __shfl_xor_sync(0xFFFFFFFFu, S22, o);
            S2  += __shfl_xor_sync(0xFFFFFFFFu, S2, o);
            mx1 = fmaxf(mx1, __shfl_xor_sync(0xFFFFFFFFu, mx1, o));
            mn1 = fminf(mn1, __shfl_xor_sync(0xFFFFFFFFu, mn1, o));
            mx2 = fmaxf(mx2, __shfl_xor_sync(0xFFFFFFFFu, mx2, o));
            mn2 = fminf(mn2, __shfl_xor_sync(0xFFFFFFFFu, mn2, o));
        }
        if (lane == 0) {
            sS[wb][0] = S11; sS[wb][1] = S12; sS[wb][2] = S1;
            sS[wb][3] = S22; sS[wb][4] = S2;
            sdegen[wb] = (((mx1 - mn1) < 1e-6f) && ((mx2 - mn2) < 1e-6f)) ? 1 : 0;
        }
    }
    asm volatile("cp.async.wait_group 0;\n" ::: "memory");       // all strips resident
    __syncthreads();

    // ---- fused stage: register carry of raw x; unroll 2 for ILP ----
    {
        float carry = scarry[tid];
        #pragma unroll 2
        for (int wb = 0; wb < 4; wb++) {
            // cofactors of AT_A (uniform per warp; identity when det==0)
            const float A00 = sS[wb][0], A01 = sS[wb][1], A02 = sS[wb][2];
            const float A11 = sS[wb][3], A12 = sS[wb][4], A22 = 64.0f;
            float C00 = A11 * A22 - A12 * A12;
            float C01 = A02 * A12 - A01 * A22;
            float C02 = A01 * A12 - A02 * A11;
            float C11 = A00 * A22 - A02 * A02;
            float C12 = A01 * A02 - A00 * A12;
            float C22 = A00 * A11 - A01 * A01;
            float det = A00 * C00 + A01 * C01 + A02 * C02;
            float rdet;
            if (det == 0.0f) {
                C00 = 1.0f; C01 = 0.0f; C02 = 0.0f;
                C11 = 1.0f; C12 = 0.0f; C22 = 1.0f;
                rdet = 1.0f;
            } else {
                rdet = __fdiv_rn(1.0f, det);
            }

            float4 v0 = *reinterpret_cast<const float4*>(&ss[tid][wb << 3]);
            float4 v1 = *reinterpret_cast<const float4*>(&ss[tid][(wb << 3) + 4]);
            float xv[8] = {v0.x, v0.y, v0.z, v0.w, v1.x, v1.y, v1.z, v1.w};
            const float lcar = carry;       // raw left pixel for this block
            carry = xv[7];                  // propagate RAW x (not output!)

            // dequant own 8 px (registers)
            float d1v[8];
            {
                float prev = lcar;
                #pragma unroll
                for (int c = 0; c < 8; c++) {
                    float xd = __fsub_rn(xv[c], prev);
                    prev = xv[c];
                    if (neq) {
                        float q = rintf(__fmul_rn(__fsub_rn(xd, mn), scale));
                        d1v[c] = __fadd_rn(__fmul_rn(q, s_inv), m);
                    } else {
                        d1v[c] = xd;
                    }
                }
            }

            // a1/a2 for this row
            float4 a1a4 = *reinterpret_cast<const float4*>(&sa[0][row][wb << 3]);
            float4 a1b4 = *reinterpret_cast<const float4*>(&sa[0][row][(wb << 3) + 4]);
            float4 a2a4 = *reinterpret_cast<const float4*>(&sa[1][row][wb << 3]);
            float4 a2b4 = *reinterpret_cast<const float4*>(&sa[1][row][(wb << 3) + 4]);
            float av1[8] = {a1a4.x, a1a4.y, a1a4.z, a1a4.w, a1b4.x, a1b4.y, a1b4.z, a1b4.w};
            float av2[8] = {a2a4.x, a2a4.y, a2a4.z, a2a4.w, a2b4.x, a2b4.y, a2b4.z, a2b4.w};

            // q = A^T d : three cheap dots (3 FMA/px)
            float t0 = 0.0f, t1 = 0.0f, t2 = 0.0f;
            #pragma unroll
            for (int c = 0; c < 8; c++) {
                t0 += av1[c] * d1v[c];
                t1 += av2[c] * d1v[c];
                t2 += d1v[c];
            }
            // reduce over the 8 lanes of this image: every lane ends with same q
            #pragma unroll
            for (int o = 4; o; o >>= 1) {
                t0 += __shfl_xor_sync(0xFFFFFFFFu, t0, o);
                t1 += __shfl_xor_sync(0xFFFFFFFFu, t1, o);
                t2 += __shfl_xor_sync(0xFFFFFFFFu, t2, o);
            }
            // p = inv * q (applied once, not per-pixel)
            const float p0 = (C00 * t0 + C01 * t1 + C02 * t2) * rdet;
            const float p1 = (C01 * t0 + C11 * t1 + C12 * t2) * rdet;
            const float p2 = (C02 * t0 + C12 * t1 + C22 * t2) * rdet;

            // reconstruct + quantize + loss
            float r1v[8];
            float loss = 0.0f;
            #pragma unroll
            for (int c = 0; c < 8; c++) {
                float r = av1[c] * p0 + av2[c] * p1 + p2;
                r1v[c] = __fmul_rn(rintf(__fmul_rn(r, rlsb)), lsb);
                float d = d1v[c] - r1v[c];
                loss += d * d;
            }
            #pragma unroll
            for (int o = 4; o; o >>= 1)
                loss += __shfl_xor_sync(0xFFFFFFFFu, loss, o);

            bool sel = (sdegen[wb] == 0) && (loss <= LOSS_THR);
            float ov[8];
            #pragma unroll
            for (int c = 0; c < 8; c++) {
                float rr = sel ? r1v[c] : d1v[c];
                float xl = (c == 0) ? lcar : xv[c - 1];
                ov[c] = __fadd_rn(rr, xl);
            }
            *reinterpret_cast<float4*>(&ss[tid][wb << 3]) =
                make_float4(ov[0], ov[1], ov[2], ov[3]);
            *reinterpret_cast<float4*>(&ss[tid][(wb << 3) + 4]) =
                make_float4(ov[4], ov[5], ov[6], ov[7]);
        }
    }
    __syncthreads();

    // ---- coalesced staged store: smem -> global (strength-reduced) ----
    {
        float* op = out + io_goff;
        const float* sp = &ss[io_srow][io_j4];
        #pragma unroll
        for (int k = 0; k < 8; k++) {
            float4 v = *reinterpret_cast<const float4*>(sp);
            *reinterpret_cast<float4*>(op) = v;
            op += (4l << 20);
            sp += 32 * 36;
        }
    }
}

extern "C" void kernel_launch(void* const* d_in, const int* in_sizes, int n_in,
                              void* d_out, int out_size) {
    const float* x = (const float*)d_in[0];
    float* out = (float*)d_out;
    (void)in_sizes; (void)n_in; (void)out_size;

    minmax_kernel<<<MM_BLOCKS, 256>>>(x);
    block_kernel<<<NHB * NWBG, 256>>>(x, out);
}

// round 17
// speedup vs baseline: 1.0560x; 1.0466x over previous
#include <cuda_runtime.h>
#include <math.h>
#include <stdint.h>

#define IMG 32
#define HDIM 1024
#define WDIM 1024
#define LOSS_THR 120.0f
#define MM_BLOCKS 1024
#define NWBG 32          // 1024 / 32 px per CTA
#define NHB 128

// ---- global scratch (module-scope: no runtime allocations) ----
__device__ float g_part_max[MM_BLOCKS];
__device__ float g_part_min[MM_BLOCKS];
__device__ unsigned int g_count = 0;   // self-resetting -> deterministic across graph replays
__device__ float g_mx;
__device__ float g_mn;

__device__ __forceinline__ unsigned int smem_u32(const void* p) {
    return (unsigned int)__cvta_generic_to_shared(p);
}

// Phase A: global min/max of width-deltas xd = x - shift_right(x).
__global__ __launch_bounds__(256) void minmax_kernel(const float* __restrict__ x) {
    const int tid = threadIdx.x;
    const int lane = tid & 31;
    const int warp = tid >> 5;
    const int base = (blockIdx.x * blockDim.x + tid) << 5;   // 32 floats per thread

    float4 v[8];
    #pragma unroll
    for (int j = 0; j < 8; j++)
        v[j] = *reinterpret_cast<const float4*>(x + base + (j << 2));
    float left = ((base & (WDIM - 1)) == 0) ? 0.0f : __ldg(x + base - 1);

    float vmax = -3.402823466e38f, vmin = 3.402823466e38f;
    #pragma unroll
    for (int j = 0; j < 8; j++) {
        float d0 = v[j].x - left;
        float d1 = v[j].y - v[j].x;
        float d2 = v[j].z - v[j].y;
        float d3 = v[j].w - v[j].z;
        left = v[j].w;
        vmax = fmaxf(fmaxf(fmaxf(d0, d1), fmaxf(d2, d3)), vmax);
        vmin = fminf(fminf(fminf(d0, d1), fminf(d2, d3)), vmin);
    }
    for (int o = 16; o; o >>= 1) {
        vmax = fmaxf(vmax, __shfl_xor_sync(0xFFFFFFFFu, vmax, o));
        vmin = fminf(vmin, __shfl_xor_sync(0xFFFFFFFFu, vmin, o));
    }
    __shared__ float swmax[8], swmin[8];
    if (lane == 0) { swmax[warp] = vmax; swmin[warp] = vmin; }
    __syncthreads();
    if (tid == 0) {
        float bmax = swmax[0], bmin = swmin[0];
        #pragma unroll
        for (int k = 1; k < 8; k++) {
            bmax = fmaxf(bmax, swmax[k]);
            bmin = fminf(bmin, swmin[k]);
        }
        g_part_max[blockIdx.x] = bmax;
        g_part_min[blockIdx.x] = bmin;
    }

    __shared__ bool isLast;
    if (tid == 0) {
        __threadfence();
        unsigned int c = atomicAdd(&g_count, 1u);
        isLast = (c == gridDim.x - 1);
    }
    __syncthreads();
    if (isLast) {
        float mx = -3.402823466e38f, mn = 3.402823466e38f;
        for (int j = tid; j < MM_BLOCKS; j += blockDim.x) {
            mx = fmaxf(mx, g_part_max[j]);
            mn = fminf(mn, g_part_min[j]);
        }
        for (int o = 16; o; o >>= 1) {
            mx = fmaxf(mx, __shfl_xor_sync(0xFFFFFFFFu, mx, o));
            mn = fminf(mn, __shfl_xor_sync(0xFFFFFFFFu, mn, o));
        }
        if (lane == 0) { swmax[warp] = mx; swmin[warp] = mn; }
        __syncthreads();
        if (tid == 0) {
            float bmax = swmax[0], bmin = swmin[0];
            #pragma unroll
            for (int k = 1; k < 8; k++) {
                bmax = fmaxf(bmax, swmax[k]);
                bmin = fminf(bmin, swmin[k]);
            }
            g_mx = bmax;
            g_mn = bmin;
            g_count = 0;  // reset for next replay
        }
    }
}

// Phase B: one CTA per (hb, group of 4 adjacent 8x8 blocks).
// Reversed tile order (L2 reuse of minmax's tail); per-warp store (no final barrier).
__global__ __launch_bounds__(256, 4) void block_kernel(const float* __restrict__ x,
                                                       float* __restrict__ out) {
    __shared__ float ss[256][36];       // raw x strips (img*8+row) x 32 px; later final output
    __shared__ float scarry[256];       // left-boundary pixel per strip
    __shared__ float sa[2][8][36];      // d1 of imgs 0,1: [img][row][wb*8+c]
    __shared__ float sS[4][5];          // Gram scalars per sub-block
    __shared__ int   sdegen[4];

    const int tid = threadIdx.x;
    const int lane = tid & 31;
    const int warp = tid >> 5;
    const int img = tid >> 3;          // image 0..31
    const int row = tid & 7;           // row 0..7
    // reversed tile order: early CTAs hit the L2-resident tail left by minmax
    const int bid = (NHB * NWBG - 1) - blockIdx.x;
    const int wbg = bid & (NWBG - 1);
    const int hb = bid >> 5;

    const float mx = g_mx, mn = g_mn;
    const bool neq = (mx != mn);
    const float scale = neq ? __fdiv_rn(65535.0f, __fsub_rn(mx, mn)) : 1.0f;
    const float s_inv = __fdiv_rn(1.0f, scale);
    const float m = neq ? mn : 0.0f;
    const float lsb = exp2f(rintf(log2f(__fdiv_rn(mx, 32768.0f))) + 1.0f);
    const float rlsb = __fdiv_rn(1.0f, lsb);

    // I/O loop geometry (loop-invariant parts; per-k: +4<<20 global, +32 rows smem)
    const int io_sr = (tid >> 3) & 7;           // spatial row (invariant over k)
    const int io_j4 = (tid & 7) << 2;           // float offset within strip (invariant)
    const long io_goff = ((long)(tid >> 6) << 20)
                       + (((hb << 3) + io_sr) << 10) + (wbg << 5) + io_j4;
    const int io_srow = tid >> 3;               // starting smem strip

    // ---- staged load, two groups: k=0 (strips 0-31, imgs 0-3) first ----
    {
        const float* gp = x + io_goff;
        unsigned int sp_ = smem_u32(&ss[io_srow][io_j4]);
        asm volatile("cp.async.cg.shared.global [%0], [%1], 16;\n"
                     :: "r"(sp_), "l"(gp) : "memory");
        asm volatile("cp.async.commit_group;\n" ::: "memory");   // group A
        gp += (4l << 20);
        sp_ += 32 * 36 * 4;
        #pragma unroll
        for (int k = 1; k < 8; k++) {
            asm volatile("cp.async.cg.shared.global [%0], [%1], 16;\n"
                         :: "r"(sp_), "l"(gp) : "memory");
            gp += (4l << 20);
            sp_ += 32 * 36 * 4;
        }
        asm volatile("cp.async.commit_group;\n" ::: "memory");   // group B
    }
    scarry[tid] = (wbg > 0)
        ? __ldg(x + (img << 20) + (((hb << 3) + row) << 10) + (wbg << 5) - 1)
        : 0.0f;
    asm volatile("cp.async.wait_group 1;\n" ::: "memory");       // group A done
    __syncthreads();

    // ---- stage A0 (128 threads): d1 of images 0,1 -> sa (4 px per thread) ----
    if (tid < 128) {
        const int im = tid >> 6;              // image 0/1
        const int ar = (tid >> 3) & 7;        // row
        const int aw = tid & 7;               // 4-px chunk 0..7
        const int strip = (im << 3) + ar;
        float4 v = *reinterpret_cast<const float4*>(&ss[strip][aw << 2]);
        float xv[4] = {v.x, v.y, v.z, v.w};
        float prev = (aw == 0) ? scarry[strip] : ss[strip][(aw << 2) - 1];
        float dq[4];
        #pragma unroll
        for (int c = 0; c < 4; c++) {
            float xd = __fsub_rn(xv[c], prev);
            prev = xv[c];
            if (neq) {
                float q = rintf(__fmul_rn(__fsub_rn(xd, mn), scale));
                dq[c] = __fadd_rn(__fmul_rn(q, s_inv), m);
            } else {
                dq[c] = xd;
            }
        }
        *reinterpret_cast<float4*>(&sa[im][ar][aw << 2]) =
            make_float4(dq[0], dq[1], dq[2], dq[3]);
    }
    __syncthreads();

    // ---- stage A1: Gram + degeneracy, warp w -> sub-block w ----
    if (warp < 4) {
        const int wb = warp;
        int r0 = lane >> 3, c0 = (wb << 3) + (lane & 7);
        float a1a = sa[0][r0][c0],     a1b = sa[0][r0 + 4][c0];
        float a2a = sa[1][r0][c0],     a2b = sa[1][r0 + 4][c0];
        float S11 = a1a * a1a + a1b * a1b;
        float S12 = a1a * a2a + a1b * a2b;
        float S1  = a1a + a1b;
        float S22 = a2a * a2a + a2b * a2b;
        float S2  = a2a + a2b;
        float mx1 = fmaxf(a1a, a1b), mn1 = fminf(a1a, a1b);
        float mx2 = fmaxf(a2a, a2b), mn2 = fminf(a2a, a2b);
        for (int o = 16; o; o >>= 1) {
            S11 += __shfl_xor_sync(0xFFFFFFFFu, S11, o);
            S12 += __shfl_xor_sync(0xFFFFFFFFu, S12, o);
            S1  += __shfl_xor_sync(0xFFFFFFFFu, S1, o);
            S22 += __shfl_xor_sync(0xFFFFFFFFu, S22, o);
            S2  += __shfl_xor_sync(0xFFFFFFFFu, S2, o);
            mx1 = fmaxf(mx1, __shfl_xor_sync(0xFFFFFFFFu, mx1, o));
            mn1 = fminf(mn1, __shfl_xor_sync(0xFFFFFFFFu, mn1, o));
            mx2 = fmaxf(mx2, __shfl_xor_sync(0xFFFFFFFFu, mx2, o));
            mn2 = fminf(mn2, __shfl_xor_sync(0xFFFFFFFFu, mn2, o));
        }
        if (lane == 0) {
            sS[wb][0] = S11; sS[wb][1] = S12; sS[wb][2] = S1;
            sS[wb][3] = S22; sS[wb][4] = S2;
            sdegen[wb] = (((mx1 - mn1) < 1e-6f) && ((mx2 - mn2) < 1e-6f)) ? 1 : 0;
        }
    }
    asm volatile("cp.async.wait_group 0;\n" ::: "memory");       // all strips resident
    __syncthreads();

    // ---- fused stage: register carry of raw x; unroll 2 for ILP ----
    {
        float carry = scarry[tid];
        #pragma unroll 2
        for (int wb = 0; wb < 4; wb++) {
            // cofactors of AT_A (uniform per warp; identity when det==0)
            const float A00 = sS[wb][0], A01 = sS[wb][1], A02 = sS[wb][2];
            const float A11 = sS[wb][3], A12 = sS[wb][4], A22 = 64.0f;
            float C00 = A11 * A22 - A12 * A12;
            float C01 = A02 * A12 - A01 * A22;
            float C02 = A01 * A12 - A02 * A11;
            float C11 = A00 * A22 - A02 * A02;
            float C12 = A01 * A02 - A00 * A12;
            float C22 = A00 * A11 - A01 * A01;
            float det = A00 * C00 + A01 * C01 + A02 * C02;
            float rdet;
            if (det == 0.0f) {
                C00 = 1.0f; C01 = 0.0f; C02 = 0.0f;
                C11 = 1.0f; C12 = 0.0f; C22 = 1.0f;
                rdet = 1.0f;
            } else {
                rdet = __fdiv_rn(1.0f, det);
            }

            float4 v0 = *reinterpret_cast<const float4*>(&ss[tid][wb << 3]);
            float4 v1 = *reinterpret_cast<const float4*>(&ss[tid][(wb << 3) + 4]);
            float xv[8] = {v0.x, v0.y, v0.z, v0.w, v1.x, v1.y, v1.z, v1.w};
            const float lcar = carry;       // raw left pixel for this block
            carry = xv[7];                  // propagate RAW x (not output!)

            // dequant own 8 px (registers)
            float d1v[8];
            {
                float prev = lcar;
                #pragma unroll
                for (int c = 0; c < 8; c++) {
                    float xd = __fsub_rn(xv[c], prev);
                    prev = xv[c];
                    if (neq) {
                        float q = rintf(__fmul_rn(__fsub_rn(xd, mn), scale));
                        d1v[c] = __fadd_rn(__fmul_rn(q, s_inv), m);
                    } else {
                        d1v[c] = xd;
                    }
                }
            }

            // a1/a2 for this row
            float4 a1a4 = *reinterpret_cast<const float4*>(&sa[0][row][wb << 3]);
            float4 a1b4 = *reinterpret_cast<const float4*>(&sa[0][row][(wb << 3) + 4]);
            float4 a2a4 = *reinterpret_cast<const float4*>(&sa[1][row][wb << 3]);
            float4 a2b4 = *reinterpret_cast<const float4*>(&sa[1][row][(wb << 3) + 4]);
            float av1[8] = {a1a4.x, a1a4.y, a1a4.z, a1a4.w, a1b4.x, a1b4.y, a1b4.z, a1b4.w};
            float av2[8] = {a2a4.x, a2a4.y, a2a4.z, a2a4.w, a2b4.x, a2b4.y, a2b4.z, a2b4.w};

            // q = A^T d : three cheap dots (3 FMA/px)
            float t0 = 0.0f, t1 = 0.0f, t2 = 0.0f;
            #pragma unroll
            for (int c = 0; c < 8; c++) {
                t0 += av1[c] * d1v[c];
                t1 += av2[c] * d1v[c];
                t2 += d1v[c];
            }
            // reduce over the 8 lanes of this image: every lane ends with same q
            #pragma unroll
            for (int o = 4; o; o >>= 1) {
                t0 += __shfl_xor_sync(0xFFFFFFFFu, t0, o);
                t1 += __shfl_xor_sync(0xFFFFFFFFu, t1, o);
                t2 += __shfl_xor_sync(0xFFFFFFFFu, t2, o);
            }
            // p = inv * q (applied once, not per-pixel)
            const float p0 = (C00 * t0 + C01 * t1 + C02 * t2) * rdet;
            const float p1 = (C01 * t0 + C11 * t1 + C12 * t2) * rdet;
            const float p2 = (C02 * t0 + C12 * t1 + C22 * t2) * rdet;

            // reconstruct + quantize + loss
            float r1v[8];
            float loss = 0.0f;
            #pragma unroll
            for (int c = 0; c < 8; c++) {
                float r = av1[c] * p0 + av2[c] * p1 + p2;
                r1v[c] = __fmul_rn(rintf(__fmul_rn(r, rlsb)), lsb);
                float d = d1v[c] - r1v[c];
                loss += d * d;
            }
            #pragma unroll
            for (int o = 4; o; o >>= 1)
                loss += __shfl_xor_sync(0xFFFFFFFFu, loss, o);

            bool sel = (sdegen[wb] == 0) && (loss <= LOSS_THR);
            float ov[8];
            #pragma unroll
            for (int c = 0; c < 8; c++) {
                float rr = sel ? r1v[c] : d1v[c];
                float xl = (c == 0) ? lcar : xv[c - 1];
                ov[c] = __fadd_rn(rr, xl);
            }
            *reinterpret_cast<float4*>(&ss[tid][wb << 3]) =
                make_float4(ov[0], ov[1], ov[2], ov[3]);
            *reinterpret_cast<float4*>(&ss[tid][(wb << 3) + 4]) =
                make_float4(ov[4], ov[5], ov[6], ov[7]);
        }
    }
    __syncwarp();

    // ---- per-warp coalesced store: warp w owns strips [32w, 32w+32) ----
    // (no CTA barrier needed: each warp stores only data its own lanes wrote)
    {
        const int sseg0 = (warp << 5) + (lane >> 3);   // first strip this lane touches
        const int j4 = (lane & 7) << 2;                // float offset within strip
        const float* sp = &ss[sseg0][j4];
        // global addr for strip sseg0: img = sseg0>>3, row = sseg0&7
        float* op = out + ((long)(sseg0 >> 3) << 20)
                  + (((hb << 3) + (sseg0 & 7)) << 10) + (wbg << 5) + j4;
        #pragma unroll
        for (int k = 0; k < 8; k++) {
            // strips advance by 4 per pass: +4 strips = same img until 8-boundary...
            // 4 strips = +4 rows within img when (sseg0&7)+4k wraps — use full recompute
            int seg = sseg0 + (k << 2);
            float4 v = *reinterpret_cast<const float4*>(&ss[seg][j4]);
            *reinterpret_cast<float4*>(
                out + ((long)(seg >> 3) << 20)
                    + (((hb << 3) + (seg & 7)) << 10) + (wbg << 5) + j4) = v;
        }
        (void)sp; (void)op;
    }
}

extern "C" void kernel_launch(void* const* d_in, const int* in_sizes, int n_in,
                              void* d_out, int out_size) {
    const float* x = (const float*)d_in[0];
    float* out = (float*)d_out;
    (void)in_sizes; (void)n_in; (void)out_size;

    minmax_kernel<<<MM_BLOCKS, 256>>>(x);
    block_kernel<<<NHB * NWBG, 256>>>(x, out);
}